// round 16
// baseline (speedup 1.0000x reference)
#include <cuda_runtime.h>
#include <math.h>

// HardNegativeContrastiveLoss, B=8192, D=128, T=0.1, margin=0.5.
//
// Identity (R3): the reference leaves the diagonal of neg_sim unmasked, so
// hardest_neg[i] == 1/T exactly for any input. The O(B^2 D) GEMM vanishes:
//   loss = (1/B) * sum_i relu(10.5 - dot(z1_i,z2_i)/(||z1_i||*||z2_i||))
//
// R14: evidence says ~4.9us is fixed per-kernel floor and the stream phase
// already runs at ~88% of HBM roofline; the atomic train is hidden by block
// arrival spread (R8). Remaining lever: the straggler block's post-load
// critical path. Replace 2x sqrt + div with one MUFU.RSQ (dp*rsqrt(ss1*ss2))
// and keep the fastest measured shape (512x256, 2 rows/warp, __ldcs,
// value-through-atomic packed completion).

#define BB       8192
#define DD       128
#define THREADS  256
#define NWARPS   (THREADS / 32)
#define ROWS_PER_WARP 2
#define NBLK     512                  // 512 * 8 warps * 2 rows = 8192 rows
#define FIXSCALE 1048576.0f           // 2^20; total < 2^37, <<16 fits in 2^53

__device__ unsigned long long g_acc;  // zero-init at load; completer resets to 0

__global__ __launch_bounds__(THREADS)
void hncl_fused(const float* __restrict__ z1, const float* __restrict__ z2,
                float* __restrict__ out) {
    const int lane = threadIdx.x & 31;
    const int warp = threadIdx.x >> 5;                         // 0..7
    const int row0 = (blockIdx.x * NWARPS + warp) * ROWS_PER_WARP;

    // 4 independent coalesced 512B warp-loads in flight (evict-first stream).
    float4 a[ROWS_PER_WARP], b[ROWS_PER_WARP];
    #pragma unroll
    for (int k = 0; k < ROWS_PER_WARP; k++) {
        a[k] = __ldcs(reinterpret_cast<const float4*>(z1 + (size_t)(row0 + k) * DD) + lane);
        b[k] = __ldcs(reinterpret_cast<const float4*>(z2 + (size_t)(row0 + k) * DD) + lane);
    }

    float ss1[ROWS_PER_WARP], ss2[ROWS_PER_WARP], dp[ROWS_PER_WARP];
    #pragma unroll
    for (int k = 0; k < ROWS_PER_WARP; k++) {
        ss1[k] = a[k].x*a[k].x + a[k].y*a[k].y + a[k].z*a[k].z + a[k].w*a[k].w;
        ss2[k] = b[k].x*b[k].x + b[k].y*b[k].y + b[k].z*b[k].z + b[k].w*b[k].w;
        dp[k]  = a[k].x*b[k].x + a[k].y*b[k].y + a[k].z*b[k].z + a[k].w*b[k].w;
    }

    // 6 independent shuffle chains interleave; latency of one 5-level tree.
    #pragma unroll
    for (int o = 16; o > 0; o >>= 1) {
        #pragma unroll
        for (int k = 0; k < ROWS_PER_WARP; k++) {
            ss1[k] += __shfl_xor_sync(0xFFFFFFFFu, ss1[k], o);
            ss2[k] += __shfl_xor_sync(0xFFFFFFFFu, ss2[k], o);
            dp[k]  += __shfl_xor_sync(0xFFFFFFFFu, dp[k],  o);
        }
    }

    __shared__ float sacc[NWARPS];
    if (lane == 0) {
        float s = 0.0f;
        #pragma unroll
        for (int k = 0; k < ROWS_PER_WARP; k++) {
            // pos = dp / (max(sqrt(ss1),eps)*max(sqrt(ss2),eps))
            //     = dp * rsqrt(max(ss1*ss2, eps^4))  (one MUFU.RSQ, no div)
            const float prod = fmaxf(ss1[k] * ss2[k], 1e-24f);
            const float pos  = dp[k] * rsqrtf(prod);
            s += fmaxf(10.5f - pos, 0.0f);
        }
        sacc[warp] = s;
    }
    __syncthreads();

    if (threadIdx.x == 0) {
        // Block partial in fixed order -> identical bits every run.
        float s = 0.0f;
        #pragma unroll
        for (int w = 0; w < NWARPS; w++) s += sacc[w];

        // Pack: high bits = fixed-point sum, low 16 bits = arrival count.
        // Integer adds commute -> order-independent, deterministic total.
        const long long fx = __float2ll_rn(s * FIXSCALE);      // >= 0
        const unsigned long long contrib =
            ((unsigned long long)fx << 16) | 1ull;

        const unsigned long long oldv = atomicAdd(&g_acc, contrib);
        const unsigned long long newv = oldv + contrib;

        if ((newv & 0xFFFFull) == (unsigned long long)NBLK) {
            // This add completed the reduction; newv holds the full total.
            const double total = (double)(long long)(newv >> 16);
            out[0] = (float)(total / ((double)FIXSCALE * (double)BB));
            g_acc = 0ull;                                       // reset for replay
        }
    }
}

extern "C" void kernel_launch(void* const* d_in, const int* in_sizes, int n_in,
                              void* d_out, int out_size) {
    const float* z1 = (const float*)d_in[0];
    const float* z2 = (const float*)d_in[1];
    float* out = (float*)d_out;
    (void)in_sizes; (void)n_in; (void)out_size;

    hncl_fused<<<NBLK, THREADS>>>(z1, z2, out);
}